// round 7
// baseline (speedup 1.0000x reference)
#include <cuda_runtime.h>
#include <cstdint>

// x: (S=128, B=512, D=512) f32 ; src_mask: (B,S) int32 (nonzero = padded)
// out: (B, G=127, 2*D) f32
// left[b][g][d]  = prefix_{s<=g} x[s][b][d]*valid[b][s]
// right[b][g][d] = total[b][d] - left[b][g][d]
//
// 4-way s-split per column: each thread owns a 32-long s-chunk of one (b,d)
// column -> pref[32] in regs (~55 regs) -> 4 blocks/SM (occ ~50%) instead of
// the 1-block/SM (154-reg) monolithic version.

namespace {
constexpr int S   = 128;
constexpr int B   = 512;
constexpr int D   = 512;
constexpr int G   = S - 1;      // 127
constexpr int CH  = 4;          // s-chunks per column
constexpr int SC  = S / CH;     // 32 s per chunk
constexpr int DPB = 64;         // d-columns per block
constexpr int TPB = DPB * CH;   // 256 threads
constexpr int BLOCKS_PER_B = D / DPB;  // 8
}

__global__ __launch_bounds__(TPB, 4)
void frag_prefix_kernel(const float* __restrict__ x,
                        const int*   __restrict__ mask,
                        float*       __restrict__ out)
{
    __shared__ float valid[S];
    __shared__ float partial[CH][DPB];

    const int b    = blockIdx.x >> 3;        // / BLOCKS_PER_B
    const int dblk = blockIdx.x & 7;         // % BLOCKS_PER_B
    const int dl   = threadIdx.x & (DPB - 1);
    const int c    = threadIdx.x >> 6;       // s-chunk id, uniform per warp
    const int d    = dblk * DPB + dl;

    if (threadIdx.x < S)
        valid[threadIdx.x] = (mask[b * S + threadIdx.x] != 0) ? 0.0f : 1.0f;
    __syncthreads();

    // Load this thread's 32 s-values (coalesced across warp: consecutive d),
    // accumulate local prefix in registers. x is single-use -> streaming loads.
    const float* __restrict__ xp =
        x + (size_t)(c * SC) * (B * D) + (size_t)b * D + d;
    float pref[SC];
    float p = 0.0f;
    #pragma unroll
    for (int i = 0; i < SC; ++i) {
        p += __ldcs(xp + (size_t)i * (B * D)) * valid[c * SC + i];
        pref[i] = p;
    }

    // Exchange chunk partial sums to get carry (sum of earlier chunks) and
    // column total.
    partial[c][dl] = p;
    __syncthreads();
    float carry = 0.0f, tot = 0.0f;
    #pragma unroll
    for (int cc = 0; cc < CH; ++cc) {
        float v = partial[cc][dl];
        if (cc < c) carry += v;
        tot += v;
    }

    // Store left/right for g in this chunk's range (skip global g == 127).
    // Warp writes 32 consecutive floats = one full 128B line; streaming stores.
    float* __restrict__ op =
        out + (size_t)b * G * (2 * D) + (size_t)(c * SC) * (2 * D) + d;
    const int gmax = (c == CH - 1) ? SC - 1 : SC;
    #pragma unroll
    for (int i = 0; i < SC; ++i) {
        if (i < gmax) {
            const float l = carry + pref[i];
            __stcs(op,     l);
            __stcs(op + D, tot - l);
        }
        op += 2 * D;
    }
}

extern "C" void kernel_launch(void* const* d_in, const int* in_sizes, int n_in,
                              void* d_out, int out_size)
{
    const float* x    = (const float*)d_in[0];
    const int*   mask = (const int*)d_in[1];
    float*       out  = (float*)d_out;

    frag_prefix_kernel<<<B * BLOCKS_PER_B, TPB>>>(x, mask, out);
}

// round 8
// speedup vs baseline: 1.0380x; 1.0380x over previous
#include <cuda_runtime.h>
#include <cstdint>

// x: (S=128, B=512, D=512) f32 ; src_mask: (B,S) int32 (nonzero = padded)
// out: (B, G=127, 2*D) f32
// left[b][g][d]  = prefix_{s<=g} x[s][b][d]*valid[b][s]
// right[b][g][d] = total[b][d] - left[b][g][d]
//
// R7: 512-thread blocks over a 256-wide d-strip, 2-way s-split.
// Keeps R5's 1KB-contiguous per-g write chunks (DRAM row locality) while
// doubling resident warps/SM (8 -> 16). R6 showed narrow write chunks kill
// HBM efficiency; this keeps them wide.

namespace {
constexpr int S   = 128;
constexpr int B   = 512;
constexpr int D   = 512;
constexpr int G   = S - 1;        // 127
constexpr int CH  = 2;            // s-chunks per column
constexpr int SC  = S / CH;       // 64 s per chunk
constexpr int DPB = 256;          // d-columns per block
constexpr int TPB = DPB * CH;     // 512 threads
constexpr int BLOCKS_PER_B = D / DPB;  // 2
}

__global__ __launch_bounds__(TPB, 1)
void frag_prefix_kernel(const float* __restrict__ x,
                        const int*   __restrict__ mask,
                        float*       __restrict__ out)
{
    __shared__ float valid[S];
    __shared__ float partial[CH][DPB];

    const int b    = blockIdx.x >> 1;            // / BLOCKS_PER_B
    const int dblk = blockIdx.x & 1;
    const int dl   = threadIdx.x & (DPB - 1);    // 0..255
    const int c    = threadIdx.x >> 8;           // 0 or 1, uniform per warp
    const int d    = dblk * DPB + dl;

    if (threadIdx.x < S)
        valid[threadIdx.x] = (mask[b * S + threadIdx.x] != 0) ? 0.0f : 1.0f;
    __syncthreads();

    // Each thread loads its 64-long s-chunk of one (b,d) column (coalesced:
    // warp = 32 consecutive d). x is single-use -> streaming loads.
    const float* __restrict__ xp =
        x + (size_t)(c * SC) * (B * D) + (size_t)b * D + d;
    float pref[SC];
    float p = 0.0f;
    #pragma unroll
    for (int i = 0; i < SC; ++i) {
        p += __ldcs(xp + (size_t)i * (B * D)) * valid[c * SC + i];
        pref[i] = p;
    }

    // Exchange the two chunk sums: carry for c=1, total for both.
    partial[c][dl] = p;
    __syncthreads();
    const float p0 = partial[0][dl];
    const float p1 = partial[1][dl];
    const float tot   = p0 + p1;
    const float carry = (c == 0) ? 0.0f : p0;

    // Write left/right for this chunk's g range (global g=127 excluded).
    // Per g the whole block writes 1KB contiguous (left) + 1KB (right).
    float* __restrict__ op =
        out + (size_t)b * G * (2 * D) + (size_t)(c * SC) * (2 * D) + d;
    const int gmax = (c == CH - 1) ? SC - 1 : SC;
    #pragma unroll
    for (int i = 0; i < SC; ++i) {
        if (i < gmax) {
            const float l = carry + pref[i];
            __stcs(op,     l);
            __stcs(op + D, tot - l);
        }
        op += 2 * D;
    }
}

extern "C" void kernel_launch(void* const* d_in, const int* in_sizes, int n_in,
                              void* d_out, int out_size)
{
    const float* x    = (const float*)d_in[0];
    const int*   mask = (const int*)d_in[1];
    float*       out  = (float*)d_out;

    frag_prefix_kernel<<<B * BLOCKS_PER_B, TPB>>>(x, mask, out);
}